// round 4
// baseline (speedup 1.0000x reference)
#include <cuda_runtime.h>
#include <cuda_bf16.h>
#include <cstdint>

// ---------------------------------------------------------------------------
// Problem constants
// ---------------------------------------------------------------------------
#define BB   16
#define TT   512
#define DD   512          // UNITS
#define GG   2048         // 4*UNITS
#define QKVD 64
#define NH   8
#define HD   8
#define EPS  1e-6f

#define NROW (BB * TT)    // 8192 rows

// ---------------------------------------------------------------------------
// Scratch: device globals (no allocation allowed)
// ---------------------------------------------------------------------------
__device__ float g_xg  [NROW * GG];      // 64 MB  x@Wx + b
__device__ float g_hseq[NROW * DD];      // 16 MB  LSTM hidden sequence
__device__ float g_hp  [NROW * DD];      // 16 MB  LN1(h) + x   (skip2)
__device__ float g_q   [NROW * QKVD];
__device__ float g_k   [NROW * QKVD];
__device__ float g_v   [NROW * QKVD];
__device__ float g_ctx [NROW * QKVD];
__device__ float g_ao  [NROW * DD];      // attn out
__device__ float g_gate[NROW * DD];      // sigmoid(hp@Wg+bg)
__device__ float g_hbuf[2][BB * DD];     // ping-pong h_t broadcast
__device__ unsigned          g_barcount = 0;
__device__ volatile unsigned g_bargen   = 0;

// ---------------------------------------------------------------------------
// Generic fp32 tiled GEMM: C[M,N] = A[M,K] @ B[K,N] + bias, ACT=1 -> sigmoid
// 256 threads. Requires BM*BK == 1024 and BK*BN == 1024, and M%BM==0,
// N%BN==0, K%BK==0 (true for every use below).
// ---------------------------------------------------------------------------
template<int BM, int BN, int BK, int TM, int TN, int ACT>
__global__ void __launch_bounds__(256)
gemm_bias(const float* __restrict__ A, const float* __restrict__ B,
          const float* __restrict__ bias, float* __restrict__ C,
          int M, int N, int K)
{
    __shared__ float As[BK][BM + 4];
    __shared__ float Bs[BK][BN];

    const int tid  = threadIdx.x;
    constexpr int TX = BN / TN;
    const int tx   = tid % TX;
    const int ty   = tid / TX;
    const int row0 = blockIdx.y * BM;
    const int col0 = blockIdx.x * BN;

    float acc[TM][TN];
#pragma unroll
    for (int i = 0; i < TM; i++)
#pragma unroll
        for (int j = 0; j < TN; j++) acc[i][j] = 0.f;

    for (int k0 = 0; k0 < K; k0 += BK) {
        // A tile: exactly one float4 per thread (BM*BK == 1024)
        {
            int i  = tid * 4;
            int m  = i / BK;
            int kk = i % BK;
            float4 a4 = *(const float4*)&A[(size_t)(row0 + m) * K + k0 + kk];
            As[kk + 0][m] = a4.x;
            As[kk + 1][m] = a4.y;
            As[kk + 2][m] = a4.z;
            As[kk + 3][m] = a4.w;
        }
        // B tile: exactly one float4 per thread (BK*BN == 1024)
        {
            int i  = tid * 4;
            int kk = i / BN;
            int n  = i % BN;
            *(float4*)&Bs[kk][n] =
                *(const float4*)&B[(size_t)(k0 + kk) * N + col0 + n];
        }
        __syncthreads();
#pragma unroll
        for (int kk = 0; kk < BK; kk++) {
            float av[TM], bv[TN];
#pragma unroll
            for (int i = 0; i < TM; i++) av[i] = As[kk][ty * TM + i];
#pragma unroll
            for (int j = 0; j < TN; j++) bv[j] = Bs[kk][tx * TN + j];
#pragma unroll
            for (int i = 0; i < TM; i++)
#pragma unroll
                for (int j = 0; j < TN; j++)
                    acc[i][j] += av[i] * bv[j];
        }
        __syncthreads();
    }

#pragma unroll
    for (int i = 0; i < TM; i++) {
#pragma unroll
        for (int j = 0; j < TN; j++) {
            float r = acc[i][j] + bias[col0 + tx * TN + j];
            if (ACT) r = 1.f / (1.f + __expf(-r));
            C[(size_t)(row0 + ty * TM + i) * N + col0 + tx * TN + j] = r;
        }
    }
}

// ---------------------------------------------------------------------------
// Persistent LSTM recurrence kernel. 128 CTAs x 256 threads, CTA c owns
// hidden units u0 = 4c .. 4c+3, i.e. gate columns {g*512 + u0 + uu}.
// Each thread (dc = tid/16, jj = tid%16) holds Wh[dc*32 .. dc*32+31][col(jj)]
// in registers for the whole kernel.
// ---------------------------------------------------------------------------
__global__ void __launch_bounds__(256, 1)
lstm_kernel(const float* __restrict__ xg, const float* __restrict__ Wh)
{
    __shared__ __align__(16) float h_s[BB * DD];   // 32 KB  h_{t-1}
    __shared__ float red[8 * 16 * 16];             // 8 KB   partial sums
    __shared__ float gact[16 * 16];                // 1 KB   gate preacts

    const int tid  = threadIdx.x;
    const int lane = tid & 31;
    const int wid  = tid >> 5;
    const int u0   = blockIdx.x * 4;

    // partial-phase identity
    const int dc   = tid >> 4;                 // 0..15 (d-chunk)
    const int jp   = tid & 15;                 // 0..15 (column)
    const int colp = ((jp >> 2) * DD) + u0 + (jp & 3);

    // reduce-phase identity
    const int jr   = tid >> 4;                 // column
    const int br   = tid & 15;                 // batch
    const int colr = ((jr >> 2) * DD) + u0 + (jr & 3);

    // load Wh column chunk into registers (read Wh from DRAM exactly once)
    float w[32];
#pragma unroll
    for (int i = 0; i < 32; i++)
        w[i] = Wh[(size_t)(dc * 32 + i) * GG + colp];

    float c_reg = 0.f;   // cell state, valid for tid < 64

    for (int t = 0; t < TT; t++) {
        // prefetch xg for the reduce phase (independent of h)
        float xg_t = xg[((size_t)(br * TT) + t) * GG + colr];

        // stage h_{t-1} into shared (L2-coherent loads)
        if (t > 0) {
            const float4* src = (const float4*)(g_hbuf[(t + 1) & 1]);
            float4* dst = (float4*)h_s;
#pragma unroll
            for (int i = 0; i < 8; i++)
                dst[tid + 256 * i] = __ldcg(&src[tid + 256 * i]);
        }
        __syncthreads();

        // partial dot products: p(b) = sum_{i<32} h[b][dc*32+i] * w[i]
        if (t > 0) {
#pragma unroll 2
            for (int b = 0; b < BB; b++) {
                const float* hrow = &h_s[b * DD + dc * 32];
                float p = 0.f;
#pragma unroll
                for (int i = 0; i < 32; i++) p += hrow[i] * w[i];
                // fold dc pairs within the warp (lane+16 has dc+1, same jj)
                p += __shfl_down_sync(0xffffffffu, p, 16);
                if (lane < 16) red[(wid * 16 + lane) * 16 + b] = p;
            }
        } else {
#pragma unroll
            for (int b = 0; b < BB; b++)
                if (lane < 16) red[(wid * 16 + lane) * 16 + b] = 0.f;
        }
        __syncthreads();

        // reduce across the 8 warps + add xg -> gate preactivation
        {
            float g = xg_t;
#pragma unroll
            for (int wq = 0; wq < 8; wq++)
                g += red[(wq * 16 + jr) * 16 + br];
            gact[jr * 16 + br] = g;
        }
        __syncthreads();

        // gate nonlinearities + state update (64 threads: (uu, b))
        if (tid < 64) {
            const int b  = tid & 15;
            const int uu = tid >> 4;           // 0..3
            float gi = gact[(0 * 4 + uu) * 16 + b];
            float gf = gact[(1 * 4 + uu) * 16 + b];
            float gg = gact[(2 * 4 + uu) * 16 + b];
            float go = gact[(3 * 4 + uu) * 16 + b];
            float i_ = 1.f / (1.f + __expf(-gi));
            float f_ = 1.f / (1.f + __expf(-gf));
            float o_ = 1.f / (1.f + __expf(-go));
            float cg = tanhf(gg);
            c_reg = f_ * c_reg + i_ * cg;
            float h = o_ * tanhf(c_reg);
            __stcg(&g_hbuf[t & 1][b * DD + u0 + uu], h);
            g_hseq[((size_t)(b * TT) + t) * DD + u0 + uu] = h;
            __threadfence();
        }
        __syncthreads();

        // grid barrier (generation-based, re-entrant across graph replays)
        if (tid == 0) {
            __threadfence();
            unsigned gen = g_bargen;
            if (atomicAdd(&g_barcount, 1u) == (unsigned)(gridDim.x - 1)) {
                g_barcount = 0;
                __threadfence();
                g_bargen = gen + 1;
            } else {
                while (g_bargen == gen) { }
            }
        }
        __syncthreads();
    }
}

// ---------------------------------------------------------------------------
// LN1 + residual: out = LN(hin)*sc + bi + res      (one block per row)
// ---------------------------------------------------------------------------
__global__ void __launch_bounds__(256)
ln_add_kernel(const float* __restrict__ hin, const float* __restrict__ res,
              const float* __restrict__ sc, const float* __restrict__ bi,
              float* __restrict__ out)
{
    __shared__ float ws[8], wq[8];
    const int row = blockIdx.x;
    const int tid = threadIdx.x;

    float2 v = ((const float2*)(hin + (size_t)row * DD))[tid];
    float s = v.x + v.y;
    float q = v.x * v.x + v.y * v.y;
#pragma unroll
    for (int o = 16; o; o >>= 1) {
        s += __shfl_xor_sync(~0u, s, o);
        q += __shfl_xor_sync(~0u, q, o);
    }
    if ((tid & 31) == 0) { ws[tid >> 5] = s; wq[tid >> 5] = q; }
    __syncthreads();
    if (tid < 32) {
        float s2 = (tid < 8) ? ws[tid] : 0.f;
        float q2 = (tid < 8) ? wq[tid] : 0.f;
#pragma unroll
        for (int o = 4; o; o >>= 1) {
            s2 += __shfl_xor_sync(~0u, s2, o);
            q2 += __shfl_xor_sync(~0u, q2, o);
        }
        if (tid == 0) { ws[0] = s2; wq[0] = q2; }
    }
    __syncthreads();
    float mean = ws[0] * (1.f / (float)DD);
    float var  = wq[0] * (1.f / (float)DD) - mean * mean;
    float inv  = rsqrtf(var + EPS);

    float2 r  = ((const float2*)(res + (size_t)row * DD))[tid];
    float2 sv = ((const float2*)sc)[tid];
    float2 bv = ((const float2*)bi)[tid];
    float2 o2;
    o2.x = (v.x - mean) * inv * sv.x + bv.x + r.x;
    o2.y = (v.y - mean) * inv * sv.y + bv.y + r.y;
    ((float2*)(out + (size_t)row * DD))[tid] = o2;
}

// ---------------------------------------------------------------------------
// Final: out = LN(ao*gate + hp)*sc + bi            (one block per row)
// ---------------------------------------------------------------------------
__global__ void __launch_bounds__(256)
final_kernel(const float* __restrict__ ao, const float* __restrict__ gate,
             const float* __restrict__ hp, const float* __restrict__ sc,
             const float* __restrict__ bi, float* __restrict__ out)
{
    __shared__ float ws[8], wq[8];
    const int row = blockIdx.x;
    const int tid = threadIdx.x;

    float2 a = ((const float2*)(ao   + (size_t)row * DD))[tid];
    float2 g = ((const float2*)(gate + (size_t)row * DD))[tid];
    float2 h = ((const float2*)(hp   + (size_t)row * DD))[tid];
    float2 v;
    v.x = a.x * g.x + h.x;
    v.y = a.y * g.y + h.y;

    float s = v.x + v.y;
    float q = v.x * v.x + v.y * v.y;
#pragma unroll
    for (int o = 16; o; o >>= 1) {
        s += __shfl_xor_sync(~0u, s, o);
        q += __shfl_xor_sync(~0u, q, o);
    }
    if ((tid & 31) == 0) { ws[tid >> 5] = s; wq[tid >> 5] = q; }
    __syncthreads();
    if (tid < 32) {
        float s2 = (tid < 8) ? ws[tid] : 0.f;
        float q2 = (tid < 8) ? wq[tid] : 0.f;
#pragma unroll
        for (int o = 4; o; o >>= 1) {
            s2 += __shfl_xor_sync(~0u, s2, o);
            q2 += __shfl_xor_sync(~0u, q2, o);
        }
        if (tid == 0) { ws[0] = s2; wq[0] = q2; }
    }
    __syncthreads();
    float mean = ws[0] * (1.f / (float)DD);
    float var  = wq[0] * (1.f / (float)DD) - mean * mean;
    float inv  = rsqrtf(var + EPS);

    float2 sv = ((const float2*)sc)[tid];
    float2 bv = ((const float2*)bi)[tid];
    float2 o2;
    o2.x = (v.x - mean) * inv * sv.x + bv.x;
    o2.y = (v.y - mean) * inv * sv.y + bv.y;
    ((float2*)(out + (size_t)row * DD))[tid] = o2;
}

// ---------------------------------------------------------------------------
// Attention: grid (b=16, h=8, quarter=4), 256 threads. K/V staged transposed
// in shared; warp w handles 16 query rows; 16 scores live per lane.
// ---------------------------------------------------------------------------
__global__ void __launch_bounds__(256)
attn_kernel(const float* __restrict__ q, const float* __restrict__ k,
            const float* __restrict__ v, float* __restrict__ ctx)
{
    __shared__ float Kt[HD][TT];   // 16 KB
    __shared__ float Vt[HD][TT];   // 16 KB

    const int b    = blockIdx.x;
    const int hh   = blockIdx.y;
    const int tid  = threadIdx.x;
    const int lane = tid & 31;
    const int wid  = tid >> 5;
    const float scale = 0.35355339059327373f;   // 1/sqrt(8)

    for (int idx = tid; idx < TT * HD; idx += 256) {
        int s = idx >> 3, d = idx & 7;
        size_t off = ((size_t)(b * TT) + s) * QKVD + hh * HD + d;
        Kt[d][s] = k[off];
        Vt[d][s] = v[off];
    }
    __syncthreads();

    const int row0 = blockIdx.z * 128 + wid * 16;
    for (int r = 0; r < 16; r++) {
        const int qrow = row0 + r;
        const float* qp = &q[((size_t)(b * TT) + qrow) * QKVD + hh * HD];
        float4 q0 = *(const float4*)qp;
        float4 q1 = *(const float4*)(qp + 4);
        float qv[8];
        qv[0] = q0.x * scale; qv[1] = q0.y * scale;
        qv[2] = q0.z * scale; qv[3] = q0.w * scale;
        qv[4] = q1.x * scale; qv[5] = q1.y * scale;
        qv[6] = q1.z * scale; qv[7] = q1.w * scale;

        float sc[16];
#pragma unroll
        for (int kk = 0; kk < 16; kk++) {
            int s = kk * 32 + lane;
            float acc = 0.f;
#pragma unroll
            for (int d = 0; d < 8; d++) acc += qv[d] * Kt[d][s];
            sc[kk] = acc;
        }
        // softmax
        float m = sc[0];
#pragma unroll
        for (int kk = 1; kk < 16; kk++) m = fmaxf(m, sc[kk]);
#pragma unroll
        for (int o = 16; o; o >>= 1)
            m = fmaxf(m, __shfl_xor_sync(~0u, m, o));
        float sum = 0.f;
#pragma unroll
        for (int kk = 0; kk < 16; kk++) {
            sc[kk] = __expf(sc[kk] - m);
            sum += sc[kk];
        }
#pragma unroll
        for (int o = 16; o; o >>= 1)
            sum += __shfl_xor_sync(~0u, sum, o);

        float acc[8];
#pragma unroll
        for (int d = 0; d < 8; d++) acc[d] = 0.f;
#pragma unroll
        for (int kk = 0; kk < 16; kk++) {
            int s = kk * 32 + lane;
            float wgt = sc[kk];
#pragma unroll
            for (int d = 0; d < 8; d++) acc[d] += wgt * Vt[d][s];
        }
#pragma unroll
        for (int d = 0; d < 8; d++)
#pragma unroll
            for (int o = 16; o; o >>= 1)
                acc[d] += __shfl_xor_sync(~0u, acc[d], o);

        if (lane == 0) {
            float invs = 1.f / sum;
            float* op = &ctx[((size_t)(b * TT) + qrow) * QKVD + hh * HD];
            float4 o0 = {acc[0] * invs, acc[1] * invs, acc[2] * invs, acc[3] * invs};
            float4 o1 = {acc[4] * invs, acc[5] * invs, acc[6] * invs, acc[7] * invs};
            *(float4*)op       = o0;
            *(float4*)(op + 4) = o1;
        }
    }
}

// ---------------------------------------------------------------------------
// Launch
// ---------------------------------------------------------------------------
extern "C" void kernel_launch(void* const* d_in, const int* in_sizes, int n_in,
                              void* d_out, int out_size)
{
    (void)in_sizes; (void)n_in; (void)out_size;

    const float* x   = (const float*)d_in[0];
    const float* Wx  = (const float*)d_in[1];
    const float* Wh  = (const float*)d_in[2];
    const float* b   = (const float*)d_in[3];
    const float* l1s = (const float*)d_in[4];
    const float* l1b = (const float*)d_in[5];
    const float* Wq  = (const float*)d_in[6];
    const float* bq  = (const float*)d_in[7];
    const float* Wk  = (const float*)d_in[8];
    const float* bk  = (const float*)d_in[9];
    const float* Wv  = (const float*)d_in[10];
    const float* bv  = (const float*)d_in[11];
    const float* Wo  = (const float*)d_in[12];
    const float* bo  = (const float*)d_in[13];
    const float* Wg  = (const float*)d_in[14];
    const float* bg  = (const float*)d_in[15];
    const float* l2s = (const float*)d_in[16];
    const float* l2b = (const float*)d_in[17];
    float* out = (float*)d_out;

    float *xg, *hseq, *hp, *qb, *kb, *vb, *ctx, *ao, *gate;
    cudaGetSymbolAddress((void**)&xg,   g_xg);
    cudaGetSymbolAddress((void**)&hseq, g_hseq);
    cudaGetSymbolAddress((void**)&hp,   g_hp);
    cudaGetSymbolAddress((void**)&qb,   g_q);
    cudaGetSymbolAddress((void**)&kb,   g_k);
    cudaGetSymbolAddress((void**)&vb,   g_v);
    cudaGetSymbolAddress((void**)&ctx,  g_ctx);
    cudaGetSymbolAddress((void**)&ao,   g_ao);
    cudaGetSymbolAddress((void**)&gate, g_gate);

    // 1. xg = x @ Wx + b        [8192,2048] = [8192,512]@[512,2048]
    gemm_bias<128, 128, 8, 8, 8, 0><<<dim3(GG / 128, NROW / 128), 256>>>(
        x, Wx, b, xg, NROW, GG, DD);

    // 2. LSTM recurrence (persistent, grid barrier)
    lstm_kernel<<<128, 256>>>(xg, Wh);

    // 3. hp = LN1(hseq) + x
    ln_add_kernel<<<NROW, 256>>>(hseq, x, l1s, l1b, hp);

    // 4. q, k, v projections    [8192,64] = [8192,512]@[512,64]
    gemm_bias<64, 64, 16, 4, 4, 0><<<dim3(1, NROW / 64), 256>>>(
        hp, Wq, bq, qb, NROW, QKVD, DD);
    gemm_bias<64, 64, 16, 4, 4, 0><<<dim3(1, NROW / 64), 256>>>(
        hp, Wk, bk, kb, NROW, QKVD, DD);
    gemm_bias<64, 64, 16, 4, 4, 0><<<dim3(1, NROW / 64), 256>>>(
        hp, Wv, bv, vb, NROW, QKVD, DD);

    // 5. attention -> ctx
    attn_kernel<<<dim3(BB, NH, 4), 256>>>(qb, kb, vb, ctx);

    // 6. attn_out = ctx @ Wo + bo     [8192,512] = [8192,64]@[64,512]
    gemm_bias<128, 128, 8, 8, 8, 0><<<dim3(DD / 128, NROW / 128), 256>>>(
        ctx, Wo, bo, ao, NROW, DD, QKVD);

    // 7. gate = sigmoid(hp @ Wg + bg) [8192,512] = [8192,512]@[512,512]
    gemm_bias<128, 128, 8, 8, 8, 1><<<dim3(DD / 128, NROW / 128), 256>>>(
        hp, Wg, bg, gate, NROW, DD, DD);

    // 8. out = LN2(ao*gate + hp)
    final_kernel<<<NROW, 256>>>(ao, gate, hp, l2s, l2b, out);
}

// round 5
// speedup vs baseline: 1.0038x; 1.0038x over previous
#include <cuda_runtime.h>
#include <cuda_bf16.h>
#include <cstdint>

// ---------------------------------------------------------------------------
// Problem constants
// ---------------------------------------------------------------------------
#define BB   16
#define TT   512
#define DD   512          // UNITS
#define GG   2048         // 4*UNITS
#define QKVD 64
#define NH   8
#define HD   8
#define EPS  1e-6f

#define NROW (BB * TT)    // 8192 rows

// ---------------------------------------------------------------------------
// Scratch: device globals (no allocation allowed)
// ---------------------------------------------------------------------------
__device__ float g_xg  [NROW * GG];      // 64 MB  x@Wx + b
__device__ float g_hseq[NROW * DD];      // 16 MB  LSTM hidden sequence
__device__ float g_hp  [NROW * DD];      // 16 MB  LN1(h) + x   (skip2)
__device__ float g_q   [NROW * QKVD];
__device__ float g_k   [NROW * QKVD];
__device__ float g_v   [NROW * QKVD];
__device__ float g_ctx [NROW * QKVD];
__device__ float g_ao  [NROW * DD];      // attn out
__device__ float g_gate[NROW * DD];      // sigmoid(hp@Wg+bg)
__device__ float g_hbuf[2][BB * DD];     // ping-pong h_t broadcast
__device__ unsigned          g_barcount = 0;
__device__ volatile unsigned g_bargen   = 0;

__device__ __forceinline__ float sigm(float x)  { return 1.f / (1.f + __expf(-x)); }
__device__ __forceinline__ float tfast(float x) { return 2.f * sigm(2.f * x) - 1.f; }

// ---------------------------------------------------------------------------
// GEMM core v2: C[.,N] = A[.,K] @ B[K,N] + bias,  ACT=1 -> sigmoid
// 256 threads. Register-staged double buffering: next gmem tile is loaded
// into registers while the current smem tile is consumed.
// Requires: BM*BK % 1024 == 0, BK*BN % 1024 == 0, K % BK == 0, BK % 4 == 0.
// ---------------------------------------------------------------------------
template<int BM, int BN, int BK, int TM, int TN, int ACT>
__device__ __forceinline__ void
gemm_core(const float* __restrict__ A, const float* __restrict__ B,
          const float* __restrict__ bias, float* __restrict__ C,
          int K, int N, int row0, int col0)
{
    __shared__ float As[BK][BM + 4];
    __shared__ float Bs[BK][BN];

    constexpr int NA = BM * BK / 1024;     // float4 loads per thread (A tile)
    constexpr int NB = BK * BN / 1024;     // float4 loads per thread (B tile)
    constexpr int TX = BN / TN;

    const int tid = threadIdx.x;
    const int tx  = tid % TX;
    const int ty  = tid / TX;

    float4 ra[NA], rb[NB];

    // preload tile 0
#pragma unroll
    for (int u = 0; u < NA; u++) {
        int fa = tid + 256 * u;
        int m  = fa / (BK / 4);
        int kk = (fa % (BK / 4)) * 4;
        ra[u] = *(const float4*)&A[(size_t)(row0 + m) * K + kk];
    }
#pragma unroll
    for (int u = 0; u < NB; u++) {
        int fb = tid + 256 * u;
        int kk = fb / (BN / 4);
        int n  = (fb % (BN / 4)) * 4;
        rb[u] = *(const float4*)&B[(size_t)kk * N + col0 + n];
    }

    float acc[TM][TN];
#pragma unroll
    for (int i = 0; i < TM; i++)
#pragma unroll
        for (int j = 0; j < TN; j++) acc[i][j] = 0.f;

    for (int k0 = 0; k0 < K; k0 += BK) {
        // commit staged registers to smem
#pragma unroll
        for (int u = 0; u < NA; u++) {
            int fa = tid + 256 * u;
            int m  = fa / (BK / 4);
            int kk = (fa % (BK / 4)) * 4;
            As[kk + 0][m] = ra[u].x;
            As[kk + 1][m] = ra[u].y;
            As[kk + 2][m] = ra[u].z;
            As[kk + 3][m] = ra[u].w;
        }
#pragma unroll
        for (int u = 0; u < NB; u++) {
            int fb = tid + 256 * u;
            int kk = fb / (BN / 4);
            int n  = (fb % (BN / 4)) * 4;
            *(float4*)&Bs[kk][n] = rb[u];
        }
        __syncthreads();

        // stage next tile while computing this one
        if (k0 + BK < K) {
#pragma unroll
            for (int u = 0; u < NA; u++) {
                int fa = tid + 256 * u;
                int m  = fa / (BK / 4);
                int kk = (fa % (BK / 4)) * 4;
                ra[u] = *(const float4*)&A[(size_t)(row0 + m) * K + k0 + BK + kk];
            }
#pragma unroll
            for (int u = 0; u < NB; u++) {
                int fb = tid + 256 * u;
                int kk = fb / (BN / 4);
                int n  = (fb % (BN / 4)) * 4;
                rb[u] = *(const float4*)&B[(size_t)(k0 + BK + kk) * N + col0 + n];
            }
        }

#pragma unroll
        for (int kk = 0; kk < BK; kk++) {
            float av[TM], bv[TN];
#pragma unroll
            for (int i = 0; i < TM; i += 4) {
                float4 t = *(const float4*)&As[kk][ty * TM + i];
                av[i] = t.x; av[i + 1] = t.y; av[i + 2] = t.z; av[i + 3] = t.w;
            }
#pragma unroll
            for (int j = 0; j < TN; j += 4) {
                float4 t = *(const float4*)&Bs[kk][tx * TN + j];
                bv[j] = t.x; bv[j + 1] = t.y; bv[j + 2] = t.z; bv[j + 3] = t.w;
            }
#pragma unroll
            for (int i = 0; i < TM; i++)
#pragma unroll
                for (int j = 0; j < TN; j++)
                    acc[i][j] += av[i] * bv[j];
        }
        __syncthreads();
    }

#pragma unroll
    for (int i = 0; i < TM; i++) {
        float* crow = &C[(size_t)(row0 + ty * TM + i) * N + col0 + tx * TN];
#pragma unroll
        for (int j = 0; j < TN; j += 4) {
            float4 o;
            o.x = acc[i][j + 0] + bias[col0 + tx * TN + j + 0];
            o.y = acc[i][j + 1] + bias[col0 + tx * TN + j + 1];
            o.z = acc[i][j + 2] + bias[col0 + tx * TN + j + 2];
            o.w = acc[i][j + 3] + bias[col0 + tx * TN + j + 3];
            if (ACT) {
                o.x = sigm(o.x); o.y = sigm(o.y);
                o.z = sigm(o.z); o.w = sigm(o.w);
            }
            *(float4*)&crow[j] = o;
        }
    }
}

template<int BM, int BN, int BK, int TM, int TN, int ACT>
__global__ void __launch_bounds__(256)
gemm2_kernel(const float* __restrict__ A, const float* __restrict__ B,
             const float* __restrict__ bias, float* __restrict__ C,
             int K, int N)
{
    gemm_core<BM, BN, BK, TM, TN, ACT>(A, B, bias, C, K, N,
                                       blockIdx.y * BM, blockIdx.x * BN);
}

// Fused q/k/v projections: blockIdx.z selects (W, bias, out).
__global__ void __launch_bounds__(256)
qkv_kernel(const float* __restrict__ hp,
           const float* __restrict__ Wq, const float* __restrict__ bq,
           const float* __restrict__ Wk, const float* __restrict__ bk,
           const float* __restrict__ Wv, const float* __restrict__ bv,
           float* __restrict__ q, float* __restrict__ k, float* __restrict__ v)
{
    const float* W; const float* bi; float* C;
    if (blockIdx.z == 0)      { W = Wq; bi = bq; C = q; }
    else if (blockIdx.z == 1) { W = Wk; bi = bk; C = k; }
    else                      { W = Wv; bi = bv; C = v; }
    gemm_core<64, 64, 16, 4, 4, 0>(hp, W, bi, C, DD, QKVD,
                                   blockIdx.y * 64, blockIdx.x * 64);
}

// ---------------------------------------------------------------------------
// Persistent LSTM recurrence. 128 CTAs x 256 threads; CTA c owns hidden
// units 4c..4c+3 (16 gate columns). Thread (dc=tid/16, jp=tid%16) holds
// Wh[dc*32 .. dc*32+31][col(jp)] in registers. float4 LDS in the hot loop.
// ---------------------------------------------------------------------------
__global__ void __launch_bounds__(256, 1)
lstm_kernel(const float* __restrict__ xg, const float* __restrict__ Wh)
{
    __shared__ __align__(16) float h_s[BB * DD];   // 32 KB  h_{t-1}
    __shared__ float red[8 * 16 * 16];             // 8 KB
    __shared__ float gact[16 * 16];                // 1 KB

    const int tid  = threadIdx.x;
    const int lane = tid & 31;
    const int wid  = tid >> 5;
    const int u0   = blockIdx.x * 4;

    const int dc   = tid >> 4;                 // 0..15 (d-chunk)
    const int jp   = tid & 15;                 // 0..15 (column)
    const int colp = ((jp >> 2) * DD) + u0 + (jp & 3);

    const int jr   = tid >> 4;                 // column (reduce phase)
    const int br   = tid & 15;                 // batch
    const int colr = ((jr >> 2) * DD) + u0 + (jr & 3);

    float w[32];
#pragma unroll
    for (int i = 0; i < 32; i++)
        w[i] = Wh[(size_t)(dc * 32 + i) * GG + colp];

    float c_reg = 0.f;   // cell state (valid for tid < 64)

    for (int t = 0; t < TT; t++) {
        // prefetch xg (independent of h_{t-1})
        float xg_t = xg[((size_t)(br * TT) + t) * GG + colr];

        // stage h_{t-1} into shared (L2-coherent loads)
        if (t > 0) {
            const float4* src = (const float4*)(g_hbuf[(t + 1) & 1]);
            float4* dst = (float4*)h_s;
#pragma unroll
            for (int i = 0; i < 8; i++)
                dst[tid + 256 * i] = __ldcg(&src[tid + 256 * i]);
        }
        __syncthreads();

        // partial dot products, float4 smem reads
        if (t > 0) {
#pragma unroll 4
            for (int b = 0; b < BB; b++) {
                const float4* hr = (const float4*)&h_s[b * DD + dc * 32];
                float p = 0.f;
#pragma unroll
                for (int i = 0; i < 8; i++) {
                    float4 hv = hr[i];
                    p += hv.x * w[4 * i + 0];
                    p += hv.y * w[4 * i + 1];
                    p += hv.z * w[4 * i + 2];
                    p += hv.w * w[4 * i + 3];
                }
                p += __shfl_down_sync(0xffffffffu, p, 16);
                if (lane < 16) red[(wid * 16 + lane) * 16 + b] = p;
            }
        } else {
            if (lane < 16)
#pragma unroll
                for (int b = 0; b < BB; b++)
                    red[(wid * 16 + lane) * 16 + b] = 0.f;
        }
        __syncthreads();

        // reduce across 8 warps + add xg
        {
            float g = xg_t;
#pragma unroll
            for (int wq = 0; wq < 8; wq++)
                g += red[(wq * 16 + jr) * 16 + br];
            gact[jr * 16 + br] = g;
        }
        __syncthreads();

        // gates + state update (64 threads)
        if (tid < 64) {
            const int b  = tid & 15;
            const int uu = tid >> 4;
            float gi = gact[(0 * 4 + uu) * 16 + b];
            float gf = gact[(1 * 4 + uu) * 16 + b];
            float gg = gact[(2 * 4 + uu) * 16 + b];
            float go = gact[(3 * 4 + uu) * 16 + b];
            float i_ = sigm(gi);
            float f_ = sigm(gf);
            float o_ = sigm(go);
            float cg = tfast(gg);
            c_reg = f_ * c_reg + i_ * cg;
            float h = o_ * tfast(c_reg);
            __stcg(&g_hbuf[t & 1][b * DD + u0 + uu], h);
            g_hseq[((size_t)(b * TT) + t) * DD + u0 + uu] = h;
            __threadfence();
        }
        __syncthreads();

        // grid barrier (generation-based; 128 CTAs are all co-resident)
        if (tid == 0) {
            __threadfence();
            unsigned gen = g_bargen;
            if (atomicAdd(&g_barcount, 1u) == (unsigned)(gridDim.x - 1)) {
                g_barcount = 0;
                __threadfence();
                g_bargen = gen + 1;
            } else {
                while (g_bargen == gen) { }
            }
        }
        __syncthreads();
    }
}

// ---------------------------------------------------------------------------
// LN1 + residual: out = LN(hin)*sc + bi + res      (one block per row)
// ---------------------------------------------------------------------------
__global__ void __launch_bounds__(256)
ln_add_kernel(const float* __restrict__ hin, const float* __restrict__ res,
              const float* __restrict__ sc, const float* __restrict__ bi,
              float* __restrict__ out)
{
    __shared__ float ws[8], wq[8];
    const int row = blockIdx.x;
    const int tid = threadIdx.x;

    float2 v = ((const float2*)(hin + (size_t)row * DD))[tid];
    float s = v.x + v.y;
    float q = v.x * v.x + v.y * v.y;
#pragma unroll
    for (int o = 16; o; o >>= 1) {
        s += __shfl_xor_sync(~0u, s, o);
        q += __shfl_xor_sync(~0u, q, o);
    }
    if ((tid & 31) == 0) { ws[tid >> 5] = s; wq[tid >> 5] = q; }
    __syncthreads();
    if (tid < 32) {
        float s2 = (tid < 8) ? ws[tid] : 0.f;
        float q2 = (tid < 8) ? wq[tid] : 0.f;
#pragma unroll
        for (int o = 4; o; o >>= 1) {
            s2 += __shfl_xor_sync(~0u, s2, o);
            q2 += __shfl_xor_sync(~0u, q2, o);
        }
        if (tid == 0) { ws[0] = s2; wq[0] = q2; }
    }
    __syncthreads();
    float mean = ws[0] * (1.f / (float)DD);
    float var  = wq[0] * (1.f / (float)DD) - mean * mean;
    float inv  = rsqrtf(var + EPS);

    float2 r  = ((const float2*)(res + (size_t)row * DD))[tid];
    float2 sv = ((const float2*)sc)[tid];
    float2 bv = ((const float2*)bi)[tid];
    float2 o2;
    o2.x = (v.x - mean) * inv * sv.x + bv.x + r.x;
    o2.y = (v.y - mean) * inv * sv.y + bv.y + r.y;
    ((float2*)(out + (size_t)row * DD))[tid] = o2;
}

// ---------------------------------------------------------------------------
// Final: out = LN(ao*gate + hp)*sc + bi            (one block per row)
// ---------------------------------------------------------------------------
__global__ void __launch_bounds__(256)
final_kernel(const float* __restrict__ ao, const float* __restrict__ gate,
             const float* __restrict__ hp, const float* __restrict__ sc,
             const float* __restrict__ bi, float* __restrict__ out)
{
    __shared__ float ws[8], wq[8];
    const int row = blockIdx.x;
    const int tid = threadIdx.x;

    float2 a = ((const float2*)(ao   + (size_t)row * DD))[tid];
    float2 g = ((const float2*)(gate + (size_t)row * DD))[tid];
    float2 h = ((const float2*)(hp   + (size_t)row * DD))[tid];
    float2 v;
    v.x = a.x * g.x + h.x;
    v.y = a.y * g.y + h.y;

    float s = v.x + v.y;
    float q = v.x * v.x + v.y * v.y;
#pragma unroll
    for (int o = 16; o; o >>= 1) {
        s += __shfl_xor_sync(~0u, s, o);
        q += __shfl_xor_sync(~0u, q, o);
    }
    if ((tid & 31) == 0) { ws[tid >> 5] = s; wq[tid >> 5] = q; }
    __syncthreads();
    if (tid < 32) {
        float s2 = (tid < 8) ? ws[tid] : 0.f;
        float q2 = (tid < 8) ? wq[tid] : 0.f;
#pragma unroll
        for (int o = 4; o; o >>= 1) {
            s2 += __shfl_xor_sync(~0u, s2, o);
            q2 += __shfl_xor_sync(~0u, q2, o);
        }
        if (tid == 0) { ws[0] = s2; wq[0] = q2; }
    }
    __syncthreads();
    float mean = ws[0] * (1.f / (float)DD);
    float var  = wq[0] * (1.f / (float)DD) - mean * mean;
    float inv  = rsqrtf(var + EPS);

    float2 sv = ((const float2*)sc)[tid];
    float2 bv = ((const float2*)bi)[tid];
    float2 o2;
    o2.x = (v.x - mean) * inv * sv.x + bv.x;
    o2.y = (v.y - mean) * inv * sv.y + bv.y;
    ((float2*)(out + (size_t)row * DD))[tid] = o2;
}

// ---------------------------------------------------------------------------
// Attention: grid (b=16, h=8, quarter=4), 256 threads. K/V staged transposed
// in shared; warp w handles 16 query rows; 16 scores per lane.
// ---------------------------------------------------------------------------
__global__ void __launch_bounds__(256)
attn_kernel(const float* __restrict__ q, const float* __restrict__ k,
            const float* __restrict__ v, float* __restrict__ ctx)
{
    __shared__ float Kt[HD][TT];   // 16 KB
    __shared__ float Vt[HD][TT];   // 16 KB

    const int b    = blockIdx.x;
    const int hh   = blockIdx.y;
    const int tid  = threadIdx.x;
    const int lane = tid & 31;
    const int wid  = tid >> 5;
    const float scale = 0.35355339059327373f;   // 1/sqrt(8)

    for (int idx = tid; idx < TT * HD; idx += 256) {
        int s = idx >> 3, d = idx & 7;
        size_t off = ((size_t)(b * TT) + s) * QKVD + hh * HD + d;
        Kt[d][s] = k[off];
        Vt[d][s] = v[off];
    }
    __syncthreads();

    const int row0 = blockIdx.z * 128 + wid * 16;
    for (int r = 0; r < 16; r++) {
        const int qrow = row0 + r;
        const float* qp = &q[((size_t)(b * TT) + qrow) * QKVD + hh * HD];
        float4 q0 = *(const float4*)qp;
        float4 q1 = *(const float4*)(qp + 4);
        float qv[8];
        qv[0] = q0.x * scale; qv[1] = q0.y * scale;
        qv[2] = q0.z * scale; qv[3] = q0.w * scale;
        qv[4] = q1.x * scale; qv[5] = q1.y * scale;
        qv[6] = q1.z * scale; qv[7] = q1.w * scale;

        float sc[16];
#pragma unroll
        for (int kk = 0; kk < 16; kk++) {
            int s = kk * 32 + lane;
            float acc = 0.f;
#pragma unroll
            for (int d = 0; d < 8; d++) acc += qv[d] * Kt[d][s];
            sc[kk] = acc;
        }
        float m = sc[0];
#pragma unroll
        for (int kk = 1; kk < 16; kk++) m = fmaxf(m, sc[kk]);
#pragma unroll
        for (int o = 16; o; o >>= 1)
            m = fmaxf(m, __shfl_xor_sync(~0u, m, o));
        float sum = 0.f;
#pragma unroll
        for (int kk = 0; kk < 16; kk++) {
            sc[kk] = __expf(sc[kk] - m);
            sum += sc[kk];
        }
#pragma unroll
        for (int o = 16; o; o >>= 1)
            sum += __shfl_xor_sync(~0u, sum, o);

        float acc[8];
#pragma unroll
        for (int d = 0; d < 8; d++) acc[d] = 0.f;
#pragma unroll
        for (int kk = 0; kk < 16; kk++) {
            int s = kk * 32 + lane;
            float wgt = sc[kk];
#pragma unroll
            for (int d = 0; d < 8; d++) acc[d] += wgt * Vt[d][s];
        }
#pragma unroll
        for (int d = 0; d < 8; d++)
#pragma unroll
            for (int o = 16; o; o >>= 1)
                acc[d] += __shfl_xor_sync(~0u, acc[d], o);

        if (lane == 0) {
            float invs = 1.f / sum;
            float* op = &ctx[((size_t)(b * TT) + qrow) * QKVD + hh * HD];
            float4 o0 = {acc[0] * invs, acc[1] * invs, acc[2] * invs, acc[3] * invs};
            float4 o1 = {acc[4] * invs, acc[5] * invs, acc[6] * invs, acc[7] * invs};
            *(float4*)op       = o0;
            *(float4*)(op + 4) = o1;
        }
    }
}

// ---------------------------------------------------------------------------
// Launch
// ---------------------------------------------------------------------------
extern "C" void kernel_launch(void* const* d_in, const int* in_sizes, int n_in,
                              void* d_out, int out_size)
{
    (void)in_sizes; (void)n_in; (void)out_size;

    const float* x   = (const float*)d_in[0];
    const float* Wx  = (const float*)d_in[1];
    const float* Wh  = (const float*)d_in[2];
    const float* b   = (const float*)d_in[3];
    const float* l1s = (const float*)d_in[4];
    const float* l1b = (const float*)d_in[5];
    const float* Wq  = (const float*)d_in[6];
    const float* bq  = (const float*)d_in[7];
    const float* Wk  = (const float*)d_in[8];
    const float* bk  = (const float*)d_in[9];
    const float* Wv  = (const float*)d_in[10];
    const float* bv  = (const float*)d_in[11];
    const float* Wo  = (const float*)d_in[12];
    const float* bo  = (const float*)d_in[13];
    const float* Wg  = (const float*)d_in[14];
    const float* bg  = (const float*)d_in[15];
    const float* l2s = (const float*)d_in[16];
    const float* l2b = (const float*)d_in[17];
    float* out = (float*)d_out;

    float *xg, *hseq, *hp, *qb, *kb, *vb, *ctx, *ao, *gate;
    cudaGetSymbolAddress((void**)&xg,   g_xg);
    cudaGetSymbolAddress((void**)&hseq, g_hseq);
    cudaGetSymbolAddress((void**)&hp,   g_hp);
    cudaGetSymbolAddress((void**)&qb,   g_q);
    cudaGetSymbolAddress((void**)&kb,   g_k);
    cudaGetSymbolAddress((void**)&vb,   g_v);
    cudaGetSymbolAddress((void**)&ctx,  g_ctx);
    cudaGetSymbolAddress((void**)&ao,   g_ao);
    cudaGetSymbolAddress((void**)&gate, g_gate);

    // 1. xg = x @ Wx + b        [8192,2048] = [8192,512]@[512,2048]
    gemm2_kernel<128, 128, 16, 8, 8, 0><<<dim3(GG / 128, NROW / 128), 256>>>(
        x, Wx, b, xg, DD, GG);

    // 2. LSTM recurrence (persistent, grid barrier)
    lstm_kernel<<<128, 256>>>(xg, Wh);

    // 3. hp = LN1(hseq) + x
    ln_add_kernel<<<NROW, 256>>>(hseq, x, l1s, l1b, hp);

    // 4. fused q,k,v projections   [8192,64] = [8192,512]@[512,64]
    qkv_kernel<<<dim3(1, NROW / 64, 3), 256>>>(
        hp, Wq, bq, Wk, bk, Wv, bv, qb, kb, vb);

    // 5. attention -> ctx
    attn_kernel<<<dim3(BB, NH, 4), 256>>>(qb, kb, vb, ctx);

    // 6. attn_out = ctx @ Wo + bo     [8192,512] = [8192,64]@[64,512]
    gemm2_kernel<128, 128, 16, 8, 8, 0><<<dim3(DD / 128, NROW / 128), 256>>>(
        ctx, Wo, bo, ao, QKVD, DD);

    // 7. gate = sigmoid(hp @ Wg + bg) [8192,512] = [8192,512]@[512,512]
    gemm2_kernel<128, 128, 16, 8, 8, 1><<<dim3(DD / 128, NROW / 128), 256>>>(
        hp, Wg, bg, gate, DD, DD);

    // 8. out = LN2(ao*gate + hp)
    final_kernel<<<NROW, 256>>>(ao, gate, hp, l2s, l2b, out);
}